// round 16
// baseline (speedup 1.0000x reference)
#include <cuda_runtime.h>
#include <cuda_bf16.h>

#define D    128
#define NG   16384
#define MAXN 524288
#define MAXE 1048576
#define STRB 272              // smem row stride bytes (136 bf16) — conflict-free ldmatrix

typedef unsigned long long u64;

// ---------------- device scratch ----------------
__device__ int   d_is64[2];
__device__ float g_g  [(size_t)NG * D];
__device__ float g_gW2[(size_t)NG * D];
__device__ float g_A  [(size_t)MAXN * D];
__device__ float g_B  [(size_t)MAXN * D];

// ---------------- generic helpers ----------------
__device__ __forceinline__ long ldx(const void* p, long i, int is64) {
    if (is64) return (long)__ldg((const long long*)p + i);
    return (long)__ldg((const int*)p + i);
}
__device__ __forceinline__ float mish1(float x) {
    float t = __expf(x);
    float u = t * t + 2.f * t;
    float r = x * (u / (u + 2.f));
    return (x > 20.f) ? x : r;
}
__device__ __forceinline__ float4 mish4(float4 v) {
    v.x = mish1(v.x); v.y = mish1(v.y); v.z = mish1(v.z); v.w = mish1(v.w);
    return v;
}
__device__ __forceinline__ unsigned smem_u32(const void* p) {
    unsigned a; asm("{ .reg .u64 t; cvta.to.shared.u64 t, %1; cvt.u32.u64 %0, t; }" : "=r"(a) : "l"(p));
    return a;
}

// ---------------- warp MMA helpers (base ISA) ----------------
__device__ __forceinline__ void ldsm4(unsigned* r, unsigned addr) {
    asm volatile("ldmatrix.sync.aligned.m8n8.x4.shared.b16 {%0,%1,%2,%3}, [%4];"
        : "=r"(r[0]), "=r"(r[1]), "=r"(r[2]), "=r"(r[3]) : "r"(addr));
}
__device__ __forceinline__ void mma_bf16(float* c, const unsigned* a, unsigned b0, unsigned b1) {
    asm volatile("mma.sync.aligned.m16n8k16.row.col.f32.bf16.bf16.f32 "
        "{%0,%1,%2,%3}, {%4,%5,%6,%7}, {%8,%9}, {%0,%1,%2,%3};"
        : "+f"(c[0]), "+f"(c[1]), "+f"(c[2]), "+f"(c[3])
        : "r"(a[0]), "r"(a[1]), "r"(a[2]), "r"(a[3]), "r"(b0), "r"(b1));
}
__device__ __forceinline__ void split4(float4 v, uint2& H, uint2& L) {
    __nv_bfloat16 h0 = __float2bfloat16_rn(v.x), h1 = __float2bfloat16_rn(v.y);
    __nv_bfloat16 h2 = __float2bfloat16_rn(v.z), h3 = __float2bfloat16_rn(v.w);
    __nv_bfloat16 l0 = __float2bfloat16_rn(v.x - __bfloat162float(h0));
    __nv_bfloat16 l1 = __float2bfloat16_rn(v.y - __bfloat162float(h1));
    __nv_bfloat16 l2 = __float2bfloat16_rn(v.z - __bfloat162float(h2));
    __nv_bfloat16 l3 = __float2bfloat16_rn(v.w - __bfloat162float(h3));
    __nv_bfloat162 H01 = __halves2bfloat162(h0, h1), H23 = __halves2bfloat162(h2, h3);
    __nv_bfloat162 L01 = __halves2bfloat162(l0, l1), L23 = __halves2bfloat162(l2, l3);
    H = make_uint2(*(unsigned*)&H01, *(unsigned*)&H23);
    L = make_uint2(*(unsigned*)&L01, *(unsigned*)&L23);
}

// convert [128,128] fp32 W (row-major [k][n]) into TRANSPOSED bf16 smem [n][k] hi/lo
__device__ void conv_w(const float* __restrict__ W, char* sm, int off_h, int off_l) {
    for (int i = threadIdx.x; i < 128 * 32; i += blockDim.x) {
        int k = i >> 5, n4 = (i & 31) << 2;
        float4 v = __ldg((const float4*)&W[k * 128 + n4]);
        float vals[4] = {v.x, v.y, v.z, v.w};
        #pragma unroll
        for (int j = 0; j < 4; j++) {
            int n = n4 + j;
            __nv_bfloat16 h = __float2bfloat16_rn(vals[j]);
            __nv_bfloat16 l = __float2bfloat16_rn(vals[j] - __bfloat162float(h));
            *(__nv_bfloat16*)(sm + off_h + n * STRB + k * 2) = h;
            *(__nv_bfloat16*)(sm + off_l + n * STRB + k * 2) = l;
        }
    }
}

// ---------------- kernel 0: dtype detection ----------------
__global__ void k_detect(const unsigned* __restrict__ b, int nb, const unsigned* __restrict__ e) {
    if (threadIdx.x == 0 && blockIdx.x == 0) {
        d_is64[0] = (b[nb - 1] == 0u && b[nb - 3] == 0u) ? 1 : 0;
        d_is64[1] = (e[1] == 0u && e[3] == 0u && e[5] == 0u && e[7] == 0u) ? 1 : 0;
    }
}

// ---------------- kernel 1: segment mean ----------------
__global__ void k_pool(const float* __restrict__ x, const void* __restrict__ batch, int N) {
    int gid = blockIdx.x;
    int t = threadIdx.x;
    int is64 = d_is64[0];
    __shared__ int s_lo, s_hi;
    if (t == 0) {
        int lo = 0, hi = N;
        while (lo < hi) { int m = (lo + hi) >> 1; if (ldx(batch, m, is64) < (long)gid) lo = m + 1; else hi = m; }
        s_lo = lo;
        hi = N;
        while (lo < hi) { int m = (lo + hi) >> 1; if (ldx(batch, m, is64) < (long)gid + 1) lo = m + 1; else hi = m; }
        s_hi = lo;
    }
    __syncthreads();
    int lo = s_lo, hi = s_hi;
    float sum = 0.f;
    for (int i = lo; i < hi; i++) sum += __ldg(&x[(size_t)i * D + t]);
    float cnt = (float)(hi - lo);
    g_g[(size_t)gid * D + t] = sum / fmaxf(cnt, 1.f);
}

// ---------------- kernel 2: gW2 ; graph_rep ----------------
__global__ __launch_bounds__(256) void k_graphmm(
    const float* __restrict__ Wn, const float* __restrict__ bn,
    const float* __restrict__ Wp, const float* __restrict__ bp,
    float* __restrict__ graph_out, int G)
{
    __shared__ float gs[64][D];
    int lane = threadIdx.x & 31, wy = threadIdx.x >> 5;
    int c = lane * 4;
    for (int row0 = blockIdx.x * 64; row0 < G; row0 += gridDim.x * 64) {
        #pragma unroll
        for (int j = 0; j < 8; j++) {
            int r = wy + 8 * j;
            *(float4*)&gs[r][c] = *(const float4*)&g_g[(size_t)(row0 + r) * D + c];
        }
        __syncwarp();
        float4 acc2[8], accP[8];
        float4 bn4 = __ldg((const float4*)&bn[c]);
        float4 bp4 = __ldg((const float4*)&bp[c]);
        #pragma unroll
        for (int j = 0; j < 8; j++) { acc2[j] = bn4; accP[j] = bp4; }
        for (int k = 0; k < D; k++) {
            float4 w2 = __ldg((const float4*)&Wn[(size_t)(D + k) * D + c]);
            float4 wp = __ldg((const float4*)&Wp[(size_t)k * D + c]);
            #pragma unroll
            for (int j = 0; j < 8; j++) {
                float a = gs[wy + 8 * j][k];
                acc2[j].x = fmaf(a, w2.x, acc2[j].x); acc2[j].y = fmaf(a, w2.y, acc2[j].y);
                acc2[j].z = fmaf(a, w2.z, acc2[j].z); acc2[j].w = fmaf(a, w2.w, acc2[j].w);
                accP[j].x = fmaf(a, wp.x, accP[j].x); accP[j].y = fmaf(a, wp.y, accP[j].y);
                accP[j].z = fmaf(a, wp.z, accP[j].z); accP[j].w = fmaf(a, wp.w, accP[j].w);
            }
        }
        #pragma unroll
        for (int j = 0; j < 8; j++) {
            size_t row = row0 + wy + 8 * j;
            *(float4*)&g_gW2[row * D + c] = acc2[j];
            *(float4*)&graph_out[row * D + c] = accP[j];
        }
        __syncwarp();
    }
}

// ---------------- kernel F1: nr = mish(x@Wn1 + gW2[batch]) ----------------
// 256-row super-tiles, 32 warps, warp = 32 rows x 32 cols (2 substrips share B frags)
#define F1_SMEM 208896
__global__ __launch_bounds__(1024, 1) void k_f1(
    const float* __restrict__ x, const void* __restrict__ batch,
    const float* __restrict__ Wn, float* __restrict__ node_out, int N)
{
    extern __shared__ char sm[];
    const int SM_WH = 0, SM_WL = 34816, SM_XH = 69632, SM_XL = 139264;
    unsigned smb = smem_u32(sm);
    int tid = threadIdx.x, lane = tid & 31, wid = tid >> 5;
    int strip = wid & 7, colq = wid >> 3;       // 8 strips x 32 rows, 4 col-quarters x 32 cols
    int is64 = d_is64[0];

    conv_w(Wn, sm, SM_WH, SM_WL);
    __syncthreads();

    unsigned abase = smb + SM_XH + (strip * 32 + (lane & 15)) * STRB + (lane >> 4) * 16;
    unsigned bbase = smb + SM_WH + (colq * 32 + (lane & 7) + ((lane >> 4) & 1) * 8) * STRB + ((lane >> 3) & 1) * 16;

    int ntiles = N >> 8;
    for (int tile = blockIdx.x; tile < ntiles; tile += gridDim.x) {
        // convert x tile (256 rows): 4 threads per row, 32 cols each
        {
            int row = tid >> 2, cb = (tid & 3) * 32;
            const float* xr = x + ((size_t)tile * 256 + row) * D + cb;
            #pragma unroll
            for (int j = 0; j < 8; j++) {
                float4 v = __ldg((const float4*)(xr + j * 4));
                uint2 H, L; split4(v, H, L);
                int off = row * STRB + (cb + j * 4) * 2;
                *(uint2*)(sm + SM_XH + off) = H;
                *(uint2*)(sm + SM_XL + off) = L;
            }
        }
        __syncthreads();

        float acc[32];
        #pragma unroll
        for (int i = 0; i < 32; i++) acc[i] = 0.f;
        unsigned bh0[4], bl0[4], bh1[4], bl1[4], ah[4], al[4];
        #pragma unroll
        for (int kc = 0; kc < 8; kc++) {
            ldsm4(bh0, bbase + kc * 32);
            ldsm4(bl0, bbase + kc * 32 + (SM_WL - SM_WH));
            ldsm4(bh1, bbase + 16 * STRB + kc * 32);
            ldsm4(bl1, bbase + 16 * STRB + kc * 32 + (SM_WL - SM_WH));
            #pragma unroll
            for (int ss = 0; ss < 2; ss++) {
                unsigned aa = abase + ss * 16 * STRB + kc * 32;
                ldsm4(ah, aa);
                ldsm4(al, aa + (SM_XL - SM_XH));
                float* a0 = acc + ss * 16;
                mma_bf16(a0 + 0,  ah, bh0[0], bh0[1]);
                mma_bf16(a0 + 0,  ah, bl0[0], bl0[1]);
                mma_bf16(a0 + 0,  al, bh0[0], bh0[1]);
                mma_bf16(a0 + 4,  ah, bh0[2], bh0[3]);
                mma_bf16(a0 + 4,  ah, bl0[2], bl0[3]);
                mma_bf16(a0 + 4,  al, bh0[2], bh0[3]);
                mma_bf16(a0 + 8,  ah, bh1[0], bh1[1]);
                mma_bf16(a0 + 8,  ah, bl1[0], bl1[1]);
                mma_bf16(a0 + 8,  al, bh1[0], bh1[1]);
                mma_bf16(a0 + 12, ah, bh1[2], bh1[3]);
                mma_bf16(a0 + 12, ah, bl1[2], bl1[3]);
                mma_bf16(a0 + 12, al, bh1[2], bh1[3]);
            }
        }

        // epilogue: + gW2[batch], mish, store (cols colq*32 .. +32)
        int rl = lane >> 2, cl = (lane & 3) * 2;
        #pragma unroll
        for (int ss = 0; ss < 2; ss++) {
            size_t gr0 = (size_t)tile * 256 + strip * 32 + ss * 16 + rl;
            size_t gr1 = gr0 + 8;
            long b0 = ldx(batch, (long)gr0, is64);
            long b1 = ldx(batch, (long)gr1, is64);
            const float* gw0 = g_gW2 + (size_t)b0 * D + colq * 32;
            const float* gw1 = g_gW2 + (size_t)b1 * D + colq * 32;
            float* n0 = node_out + gr0 * D + colq * 32;
            float* n1 = node_out + gr1 * D + colq * 32;
            float* a0 = acc + ss * 16;
            #pragma unroll
            for (int nt = 0; nt < 4; nt++) {
                int col = nt * 8 + cl;
                float2 g0 = *(const float2*)&gw0[col];
                float2 g1 = *(const float2*)&gw1[col];
                float2 o0 = make_float2(mish1(a0[nt * 4 + 0] + g0.x), mish1(a0[nt * 4 + 1] + g0.y));
                float2 o1 = make_float2(mish1(a0[nt * 4 + 2] + g1.x), mish1(a0[nt * 4 + 3] + g1.y));
                *(float2*)&n0[col] = o0;
                *(float2*)&n1[col] = o1;
            }
        }
        __syncthreads();
    }
}

// ---------------- kernel F2: A=nr@We1, B=nr@We2, self ----------------
// 128-row tiles, 32 warps = 2 mats x 4 strips(32 rows) x 4 colq(32 cols)
#define F2_SMEM 208896
__global__ __launch_bounds__(1024, 1) void k_f2(
    const float* __restrict__ nr_in, const float* __restrict__ We,
    const float* __restrict__ be,
    float* __restrict__ self_out, int N)
{
    extern __shared__ char sm[];
    const int SM_W1H = 0, SM_W1L = 34816, SM_W2H = 69632, SM_W2L = 104448;
    const int SM_XH = 139264, SM_XL = 174080;
    unsigned smb = smem_u32(sm);
    int tid = threadIdx.x, lane = tid & 31, wid = tid >> 5;
    int mat = wid & 1, colq = (wid >> 1) & 3, strip = wid >> 3;

    conv_w(We, sm, SM_W1H, SM_W1L);            // We1
    conv_w(We + 128 * D, sm, SM_W2H, SM_W2L);  // We2
    __syncthreads();

    unsigned abase = smb + SM_XH + (strip * 32 + (lane & 15)) * STRB + (lane >> 4) * 16;
    unsigned wb = mat ? SM_W2H : SM_W1H;
    unsigned bbase = smb + wb + (colq * 32 + (lane & 7) + ((lane >> 4) & 1) * 8) * STRB + ((lane >> 3) & 1) * 16;
    float* exch = (float*)(sm + SM_XH);         // 128x128 f32 = 65536 B <= 69632

    int ntiles = N >> 7;
    for (int tile = blockIdx.x; tile < ntiles; tile += gridDim.x) {
        // convert nr tile (128 rows): 8 threads per row, 16 cols each
        {
            int row = tid >> 3, cb = (tid & 7) * 16;
            const float* xr = nr_in + ((size_t)tile * 128 + row) * D + cb;
            #pragma unroll
            for (int j = 0; j < 4; j++) {
                float4 v = __ldg((const float4*)(xr + j * 4));
                uint2 H, L; split4(v, H, L);
                int off = row * STRB + (cb + j * 4) * 2;
                *(uint2*)(sm + SM_XH + off) = H;
                *(uint2*)(sm + SM_XL + off) = L;
            }
        }
        __syncthreads();

        float acc[32];
        #pragma unroll
        for (int i = 0; i < 32; i++) acc[i] = 0.f;
        unsigned bh0[4], bl0[4], bh1[4], bl1[4], ah[4], al[4];
        #pragma unroll
        for (int kc = 0; kc < 8; kc++) {
            ldsm4(bh0, bbase + kc * 32);
            ldsm4(bl0, bbase + kc * 32 + 34816);
            ldsm4(bh1, bbase + 16 * STRB + kc * 32);
            ldsm4(bl1, bbase + 16 * STRB + kc * 32 + 34816);
            #pragma unroll
            for (int ss = 0; ss < 2; ss++) {
                unsigned aa = abase + ss * 16 * STRB + kc * 32;
                ldsm4(ah, aa);
                ldsm4(al, aa + (SM_XL - SM_XH));
                float* a0 = acc + ss * 16;
                mma_bf16(a0 + 0,  ah, bh0[0], bh0[1]);
                mma_bf16(a0 + 0,  ah, bl0[0], bl0[1]);
                mma_bf16(a0 + 0,  al, bh0[0], bh0[1]);
                mma_bf16(a0 + 4,  ah, bh0[2], bh0[3]);
                mma_bf16(a0 + 4,  ah, bl0[2], bl0[3]);
                mma_bf16(a0 + 4,  al, bh0[2], bh0[3]);
                mma_bf16(a0 + 8,  ah, bh1[0], bh1[1]);
                mma_bf16(a0 + 8,  ah, bl1[0], bl1[1]);
                mma_bf16(a0 + 8,  al, bh1[0], bh1[1]);
                mma_bf16(a0 + 12, ah, bh1[2], bh1[3]);
                mma_bf16(a0 + 12, ah, bl1[2], bl1[3]);
                mma_bf16(a0 + 12, al, bh1[2], bh1[3]);
            }
        }
        __syncthreads();   // all mma done; X region reused as exchange

        int rl = lane >> 2, cl = (lane & 3) * 2;

        if (mat == 0) {
            #pragma unroll
            for (int ss = 0; ss < 2; ss++) {
                int r0 = strip * 32 + ss * 16 + rl, r1 = r0 + 8;
                size_t gr0 = (size_t)tile * 128 + r0;
                size_t gr1 = (size_t)tile * 128 + r1;
                float* A0 = g_A + gr0 * D + colq * 32;
                float* A1 = g_A + gr1 * D + colq * 32;
                float* a0 = acc + ss * 16;
                #pragma unroll
                for (int nt = 0; nt < 4; nt++) {
                    int col = nt * 8 + cl;
                    float2 v0 = make_float2(a0[nt * 4 + 0], a0[nt * 4 + 1]);
                    float2 v1 = make_float2(a0[nt * 4 + 2], a0[nt * 4 + 3]);
                    *(float2*)&A0[col] = v0;
                    *(float2*)&A1[col] = v1;
                    *(float2*)&exch[r0 * 128 + colq * 32 + col] = v0;
                    *(float2*)&exch[r1 * 128 + colq * 32 + col] = v1;
                }
            }
        }
        __syncthreads();
        if (mat == 1) {
            #pragma unroll
            for (int ss = 0; ss < 2; ss++) {
                int r0 = strip * 32 + ss * 16 + rl, r1 = r0 + 8;
                size_t gr0 = (size_t)tile * 128 + r0;
                size_t gr1 = (size_t)tile * 128 + r1;
                float* B0 = g_B + gr0 * D + colq * 32;
                float* B1 = g_B + gr1 * D + colq * 32;
                float* S0 = self_out + gr0 * D + colq * 32;
                float* S1 = self_out + gr1 * D + colq * 32;
                float* a0 = acc + ss * 16;
                #pragma unroll
                for (int nt = 0; nt < 4; nt++) {
                    int col = nt * 8 + cl;
                    float2 be2 = *(const float2*)&be[colq * 32 + col];
                    float2 v0 = make_float2(a0[nt * 4 + 0], a0[nt * 4 + 1]);
                    float2 v1 = make_float2(a0[nt * 4 + 2], a0[nt * 4 + 3]);
                    *(float2*)&B0[col] = v0;
                    *(float2*)&B1[col] = v1;
                    float2 x0 = *(const float2*)&exch[r0 * 128 + colq * 32 + col];
                    float2 x1 = *(const float2*)&exch[r1 * 128 + colq * 32 + col];
                    float2 s0 = make_float2(mish1(x0.x + v0.x + be2.x), mish1(x0.y + v0.y + be2.y));
                    float2 s1 = make_float2(mish1(x1.x + v1.x + be2.x), mish1(x1.y + v1.y + be2.y));
                    *(float2*)&S0[col] = s0;
                    *(float2*)&S1[col] = s1;
                }
            }
        }
        __syncthreads();
    }
}

// ---------------- kernel 4: edges ----------------
__global__ __launch_bounds__(256) void k_edge(
    const void* __restrict__ ei, const float* __restrict__ be,
    float* __restrict__ edge_out, int E)
{
    int is64 = d_is64[1];
    int lane = threadIdx.x & 31;
    int warp = blockIdx.x * (blockDim.x >> 5) + (threadIdx.x >> 5);
    int nwarps = gridDim.x * (blockDim.x >> 5);
    int c = lane * 4;
    float4 be4 = __ldg((const float4*)&be[c]);
    int pairs = E >> 1;
    for (int p = warp; p < pairs; p += nwarps) {
        long e0 = 2L * p;
        long s0 = ldx(ei, e0, is64);
        long s1 = ldx(ei, e0 + 1, is64);
        long d0 = ldx(ei, (long)E + e0, is64);
        long d1 = ldx(ei, (long)E + e0 + 1, is64);
        float4 a0 = __ldg((const float4*)&g_A[(size_t)s0 * D + c]);
        float4 b0 = __ldg((const float4*)&g_B[(size_t)d0 * D + c]);
        float4 a1 = __ldg((const float4*)&g_A[(size_t)s1 * D + c]);
        float4 b1 = __ldg((const float4*)&g_B[(size_t)d1 * D + c]);
        float4 v0 = mish4(make_float4(a0.x + b0.x + be4.x, a0.y + b0.y + be4.y,
                                      a0.z + b0.z + be4.z, a0.w + b0.w + be4.w));
        float4 v1 = mish4(make_float4(a1.x + b1.x + be4.x, a1.y + b1.y + be4.y,
                                      a1.z + b1.z + be4.z, a1.w + b1.w + be4.w));
        float4 o = make_float4(0.5f * (v0.x + v1.x), 0.5f * (v0.y + v1.y),
                               0.5f * (v0.z + v1.z), 0.5f * (v0.w + v1.w));
        *(float4*)&edge_out[(size_t)p * D + c] = o;
    }
}

// ---------------- launch ----------------
extern "C" void kernel_launch(void* const* d_in, const int* in_sizes, int n_in,
                              void* d_out, int out_size)
{
    const float* x     = (const float*)d_in[0];
    const void*  batch = d_in[1];
    const void*  ei    = d_in[2];
    const float* Wn    = (const float*)d_in[3];
    const float* bn    = (const float*)d_in[4];
    const float* We    = (const float*)d_in[5];
    const float* bee   = (const float*)d_in[6];
    const float* Wp    = (const float*)d_in[7];
    const float* bp    = (const float*)d_in[8];

    int N = in_sizes[0] / D;
    int E = MAXE;

    float* out       = (float*)d_out;
    float* node_out  = out;
    float* self_out  = out + (size_t)N * D;
    float* edge_out  = out + 2 * (size_t)N * D;
    float* graph_out = out + 3 * (size_t)N * D;

    static int init_done = 0;
    if (!init_done) {
        cudaFuncSetAttribute(k_f1, cudaFuncAttributeMaxDynamicSharedMemorySize, F1_SMEM);
        cudaFuncSetAttribute(k_f2, cudaFuncAttributeMaxDynamicSharedMemorySize, F2_SMEM);
        init_done = 1;
    }

    k_detect<<<1, 32>>>((const unsigned*)batch, N, (const unsigned*)ei);
    k_pool<<<NG, 128>>>(x, batch, N);
    k_graphmm<<<NG / 64, 256>>>(Wn, bn, Wp, bp, graph_out, NG);
    k_f1<<<148, 1024, F1_SMEM>>>(x, batch, Wn, node_out, N);
    k_f2<<<148, 1024, F2_SMEM>>>(node_out, We, bee, self_out, N);
    k_edge<<<2048, 256>>>(ei, bee, edge_out, E);
}

// round 17
// speedup vs baseline: 1.1996x; 1.1996x over previous
#include <cuda_runtime.h>
#include <cuda_fp16.h>

#define D    128
#define NG   16384
#define MAXN 524288
#define MAXE 1048576
#define STRB 272              // smem row stride bytes (136 halves) — conflict-free ldmatrix

typedef unsigned long long u64;

// ---------------- device scratch ----------------
__device__ int   d_is64[2];
__device__ float g_g  [(size_t)NG * D];
__device__ float g_gW2[(size_t)NG * D];
__device__ float g_A  [(size_t)MAXN * D];
__device__ float g_B  [(size_t)MAXN * D];

// ---------------- generic helpers ----------------
__device__ __forceinline__ long ldx(const void* p, long i, int is64) {
    if (is64) return (long)__ldg((const long long*)p + i);
    return (long)__ldg((const int*)p + i);
}
__device__ __forceinline__ float mish1(float x) {
    float t = __expf(x);
    float u = t * t + 2.f * t;
    float r = x * (u / (u + 2.f));
    return (x > 20.f) ? x : r;
}
__device__ __forceinline__ float4 mish4(float4 v) {
    v.x = mish1(v.x); v.y = mish1(v.y); v.z = mish1(v.z); v.w = mish1(v.w);
    return v;
}
__device__ __forceinline__ unsigned smem_u32(const void* p) {
    unsigned a; asm("{ .reg .u64 t; cvta.to.shared.u64 t, %1; cvt.u32.u64 %0, t; }" : "=r"(a) : "l"(p));
    return a;
}

// ---------------- warp MMA helpers (base ISA, fp16 path) ----------------
__device__ __forceinline__ void ldsm4(unsigned* r, unsigned addr) {
    asm volatile("ldmatrix.sync.aligned.m8n8.x4.shared.b16 {%0,%1,%2,%3}, [%4];"
        : "=r"(r[0]), "=r"(r[1]), "=r"(r[2]), "=r"(r[3]) : "r"(addr));
}
__device__ __forceinline__ void mma_f16(float* c, const unsigned* a, unsigned b0, unsigned b1) {
    asm volatile("mma.sync.aligned.m16n8k16.row.col.f32.f16.f16.f32 "
        "{%0,%1,%2,%3}, {%4,%5,%6,%7}, {%8,%9}, {%0,%1,%2,%3};"
        : "+f"(c[0]), "+f"(c[1]), "+f"(c[2]), "+f"(c[3])
        : "r"(a[0]), "r"(a[1]), "r"(a[2]), "r"(a[3]), "r"(b0), "r"(b1));
}
// fp32x4 -> fp16 hi + fp16 residual, packed pairs
__device__ __forceinline__ void split4h(float4 v, uint2& H, uint2& L) {
    __half h0 = __float2half_rn(v.x), h1 = __float2half_rn(v.y);
    __half h2 = __float2half_rn(v.z), h3 = __float2half_rn(v.w);
    __half l0 = __float2half_rn(v.x - __half2float(h0));
    __half l1 = __float2half_rn(v.y - __half2float(h1));
    __half l2 = __float2half_rn(v.z - __half2float(h2));
    __half l3 = __float2half_rn(v.w - __half2float(h3));
    __half2 H01 = __halves2half2(h0, h1), H23 = __halves2half2(h2, h3);
    __half2 L01 = __halves2half2(l0, l1), L23 = __halves2half2(l2, l3);
    H = make_uint2(*(unsigned*)&H01, *(unsigned*)&H23);
    L = make_uint2(*(unsigned*)&L01, *(unsigned*)&L23);
}

// convert [128,128] fp32 W (row-major [k][n]) into TRANSPOSED fp16 smem [n][k]
__device__ void conv_w(const float* __restrict__ W, char* sm, int off) {
    for (int i = threadIdx.x; i < 128 * 32; i += blockDim.x) {
        int k = i >> 5, n4 = (i & 31) << 2;
        float4 v = __ldg((const float4*)&W[k * 128 + n4]);
        float vals[4] = {v.x, v.y, v.z, v.w};
        #pragma unroll
        for (int j = 0; j < 4; j++) {
            int n = n4 + j;
            *(__half*)(sm + off + n * STRB + k * 2) = __float2half_rn(vals[j]);
        }
    }
}

// ---------------- kernel 0: dtype detection ----------------
__global__ void k_detect(const unsigned* __restrict__ b, int nb, const unsigned* __restrict__ e) {
    if (threadIdx.x == 0 && blockIdx.x == 0) {
        d_is64[0] = (b[nb - 1] == 0u && b[nb - 3] == 0u) ? 1 : 0;
        d_is64[1] = (e[1] == 0u && e[3] == 0u && e[5] == 0u && e[7] == 0u) ? 1 : 0;
    }
}

// ---------------- kernel 1: segment mean ----------------
__global__ void k_pool(const float* __restrict__ x, const void* __restrict__ batch, int N) {
    int gid = blockIdx.x;
    int t = threadIdx.x;
    int is64 = d_is64[0];
    __shared__ int s_lo, s_hi;
    if (t == 0) {
        int lo = 0, hi = N;
        while (lo < hi) { int m = (lo + hi) >> 1; if (ldx(batch, m, is64) < (long)gid) lo = m + 1; else hi = m; }
        s_lo = lo;
        hi = N;
        while (lo < hi) { int m = (lo + hi) >> 1; if (ldx(batch, m, is64) < (long)gid + 1) lo = m + 1; else hi = m; }
        s_hi = lo;
    }
    __syncthreads();
    int lo = s_lo, hi = s_hi;
    float sum = 0.f;
    for (int i = lo; i < hi; i++) sum += __ldg(&x[(size_t)i * D + t]);
    float cnt = (float)(hi - lo);
    g_g[(size_t)gid * D + t] = sum / fmaxf(cnt, 1.f);
}

// ---------------- kernel 2: gW2 ; graph_rep ----------------
__global__ __launch_bounds__(256) void k_graphmm(
    const float* __restrict__ Wn, const float* __restrict__ bn,
    const float* __restrict__ Wp, const float* __restrict__ bp,
    float* __restrict__ graph_out, int G)
{
    __shared__ float gs[64][D];
    int lane = threadIdx.x & 31, wy = threadIdx.x >> 5;
    int c = lane * 4;
    for (int row0 = blockIdx.x * 64; row0 < G; row0 += gridDim.x * 64) {
        #pragma unroll
        for (int j = 0; j < 8; j++) {
            int r = wy + 8 * j;
            *(float4*)&gs[r][c] = *(const float4*)&g_g[(size_t)(row0 + r) * D + c];
        }
        __syncwarp();
        float4 acc2[8], accP[8];
        float4 bn4 = __ldg((const float4*)&bn[c]);
        float4 bp4 = __ldg((const float4*)&bp[c]);
        #pragma unroll
        for (int j = 0; j < 8; j++) { acc2[j] = bn4; accP[j] = bp4; }
        for (int k = 0; k < D; k++) {
            float4 w2 = __ldg((const float4*)&Wn[(size_t)(D + k) * D + c]);
            float4 wp = __ldg((const float4*)&Wp[(size_t)k * D + c]);
            #pragma unroll
            for (int j = 0; j < 8; j++) {
                float a = gs[wy + 8 * j][k];
                acc2[j].x = fmaf(a, w2.x, acc2[j].x); acc2[j].y = fmaf(a, w2.y, acc2[j].y);
                acc2[j].z = fmaf(a, w2.z, acc2[j].z); acc2[j].w = fmaf(a, w2.w, acc2[j].w);
                accP[j].x = fmaf(a, wp.x, accP[j].x); accP[j].y = fmaf(a, wp.y, accP[j].y);
                accP[j].z = fmaf(a, wp.z, accP[j].z); accP[j].w = fmaf(a, wp.w, accP[j].w);
            }
        }
        #pragma unroll
        for (int j = 0; j < 8; j++) {
            size_t row = row0 + wy + 8 * j;
            *(float4*)&g_gW2[row * D + c] = acc2[j];
            *(float4*)&graph_out[row * D + c] = accP[j];
        }
        __syncwarp();
    }
}

// ---------------- kernel F1: nr = mish(x@Wn1 + gW2[batch]) — fp16x2, 32 warps, warp=16x32 ----------------
#define F1_SMEM 104448
__global__ __launch_bounds__(1024, 1) void k_f1(
    const float* __restrict__ x, const void* __restrict__ batch,
    const float* __restrict__ Wn, float* __restrict__ node_out, int N)
{
    extern __shared__ char sm[];
    const int SM_W = 0, SM_XH = 34816, SM_XL = 69632;
    unsigned smb = smem_u32(sm);
    int tid = threadIdx.x, lane = tid & 31, wid = tid >> 5;
    int strip = wid & 7, colq = wid >> 3;       // 8 row-strips x 4 col-quarters
    int is64 = d_is64[0];

    conv_w(Wn, sm, SM_W);
    __syncthreads();

    unsigned abase = smb + SM_XH + (strip * 16 + (lane & 15)) * STRB + (lane >> 4) * 16;
    unsigned bbase = smb + SM_W + (colq * 32 + (lane & 7) + ((lane >> 4) & 1) * 8) * STRB + ((lane >> 3) & 1) * 16;

    int ntiles = N >> 7;
    for (int tile = blockIdx.x; tile < ntiles; tile += gridDim.x) {
        // convert x tile: 8 threads per row, 16 cols each
        {
            int row = tid >> 3, cb = (tid & 7) * 16;
            const float* xr = x + ((size_t)tile * 128 + row) * D + cb;
            #pragma unroll
            for (int j = 0; j < 4; j++) {
                float4 v = __ldg((const float4*)(xr + j * 4));
                uint2 H, L; split4h(v, H, L);
                int off = row * STRB + (cb + j * 4) * 2;
                *(uint2*)(sm + SM_XH + off) = H;
                *(uint2*)(sm + SM_XL + off) = L;
            }
        }
        __syncthreads();

        float acc[16];
        #pragma unroll
        for (int i = 0; i < 16; i++) acc[i] = 0.f;
        unsigned ah[4], al[4], bq[4];
        #pragma unroll
        for (int kc = 0; kc < 8; kc++) {
            ldsm4(ah, abase + kc * 32);
            ldsm4(al, abase + kc * 32 + (SM_XL - SM_XH));
            #pragma unroll
            for (int nt2 = 0; nt2 < 2; nt2++) {
                ldsm4(bq, bbase + nt2 * 16 * STRB + kc * 32);
                mma_f16(acc + 8 * nt2,     ah, bq[0], bq[1]);
                mma_f16(acc + 8 * nt2,     al, bq[0], bq[1]);
                mma_f16(acc + 8 * nt2 + 4, ah, bq[2], bq[3]);
                mma_f16(acc + 8 * nt2 + 4, al, bq[2], bq[3]);
            }
        }

        // epilogue: + gW2[batch], mish, store (cols colq*32 .. +32)
        int rl = lane >> 2, cl = (lane & 3) * 2;
        size_t gr0 = (size_t)tile * 128 + strip * 16 + rl;
        size_t gr1 = gr0 + 8;
        long b0 = ldx(batch, (long)gr0, is64);
        long b1 = ldx(batch, (long)gr1, is64);
        const float* gw0 = g_gW2 + (size_t)b0 * D + colq * 32;
        const float* gw1 = g_gW2 + (size_t)b1 * D + colq * 32;
        float* n0 = node_out + gr0 * D + colq * 32;
        float* n1 = node_out + gr1 * D + colq * 32;
        #pragma unroll
        for (int nt = 0; nt < 4; nt++) {
            int col = nt * 8 + cl;
            float2 g0 = *(const float2*)&gw0[col];
            float2 g1 = *(const float2*)&gw1[col];
            float2 o0 = make_float2(mish1(acc[nt * 4 + 0] + g0.x), mish1(acc[nt * 4 + 1] + g0.y));
            float2 o1 = make_float2(mish1(acc[nt * 4 + 2] + g1.x), mish1(acc[nt * 4 + 3] + g1.y));
            *(float2*)&n0[col] = o0;
            *(float2*)&n1[col] = o1;
        }
        __syncthreads();
    }
}

// ---------------- kernel F2: A=nr@We1, B=nr@We2, self — fp16x2, 128-row tiles, 32 warps ----------------
// warp = 16 rows x 64 cols x 1 matrix:  mat = wid&1, colh = (wid>>1)&1, strip = wid>>2
#define F2_SMEM 139264
__global__ __launch_bounds__(1024, 1) void k_f2(
    const float* __restrict__ nr_in, const float* __restrict__ We,
    const float* __restrict__ be,
    float* __restrict__ self_out, int N)
{
    extern __shared__ char sm[];
    const int SM_W1 = 0, SM_W2 = 34816, SM_XH = 69632, SM_XL = 104448;
    unsigned smb = smem_u32(sm);
    int tid = threadIdx.x, lane = tid & 31, wid = tid >> 5;
    int mat = wid & 1, colh = (wid >> 1) & 1, strip = wid >> 2;

    conv_w(We, sm, SM_W1);             // We1
    conv_w(We + 128 * D, sm, SM_W2);   // We2
    __syncthreads();

    unsigned abase = smb + SM_XH + (strip * 16 + (lane & 15)) * STRB + (lane >> 4) * 16;
    unsigned wb = mat ? SM_W2 : SM_W1;
    unsigned bbase = smb + wb + (colh * 64 + (lane & 7) + ((lane >> 4) & 1) * 8) * STRB + ((lane >> 3) & 1) * 16;
    float* exch = (float*)(sm + SM_XH);         // 128x128 f32 = 65536 B <= 69632

    int ntiles = N >> 7;
    for (int tile = blockIdx.x; tile < ntiles; tile += gridDim.x) {
        // convert nr tile: 8 threads per row, 16 cols each
        {
            int row = tid >> 3, cb = (tid & 7) * 16;
            const float* xr = nr_in + ((size_t)tile * 128 + row) * D + cb;
            #pragma unroll
            for (int j = 0; j < 4; j++) {
                float4 v = __ldg((const float4*)(xr + j * 4));
                uint2 H, L; split4h(v, H, L);
                int off = row * STRB + (cb + j * 4) * 2;
                *(uint2*)(sm + SM_XH + off) = H;
                *(uint2*)(sm + SM_XL + off) = L;
            }
        }
        __syncthreads();

        float acc[32];
        #pragma unroll
        for (int i = 0; i < 32; i++) acc[i] = 0.f;
        unsigned ah[4], al[4], bq[4];
        #pragma unroll
        for (int kc = 0; kc < 8; kc++) {
            ldsm4(ah, abase + kc * 32);
            ldsm4(al, abase + kc * 32 + (SM_XL - SM_XH));
            #pragma unroll
            for (int nt2 = 0; nt2 < 4; nt2++) {
                ldsm4(bq, bbase + nt2 * 16 * STRB + kc * 32);
                mma_f16(acc + 8 * nt2,     ah, bq[0], bq[1]);
                mma_f16(acc + 8 * nt2,     al, bq[0], bq[1]);
                mma_f16(acc + 8 * nt2 + 4, ah, bq[2], bq[3]);
                mma_f16(acc + 8 * nt2 + 4, al, bq[2], bq[3]);
            }
        }
        __syncthreads();   // all mma done; X region reused as exchange

        int rl = lane >> 2, cl = (lane & 3) * 2;
        int r0 = strip * 16 + rl, r1 = r0 + 8;
        size_t gr0 = (size_t)tile * 128 + r0;
        size_t gr1 = (size_t)tile * 128 + r1;

        if (mat == 0) {
            float* A0 = g_A + gr0 * D + colh * 64;
            float* A1 = g_A + gr1 * D + colh * 64;
            #pragma unroll
            for (int nt = 0; nt < 8; nt++) {
                int col = nt * 8 + cl;
                float2 a0 = make_float2(acc[nt * 4 + 0], acc[nt * 4 + 1]);
                float2 a1 = make_float2(acc[nt * 4 + 2], acc[nt * 4 + 3]);
                *(float2*)&A0[col] = a0;
                *(float2*)&A1[col] = a1;
                *(float2*)&exch[r0 * 128 + colh * 64 + col] = a0;
                *(float2*)&exch[r1 * 128 + colh * 64 + col] = a1;
            }
        }
        __syncthreads();
        if (mat == 1) {
            float* B0 = g_B + gr0 * D + colh * 64;
            float* B1 = g_B + gr1 * D + colh * 64;
            float* S0 = self_out + gr0 * D + colh * 64;
            float* S1 = self_out + gr1 * D + colh * 64;
            #pragma unroll
            for (int nt = 0; nt < 8; nt++) {
                int col = nt * 8 + cl;
                float2 be2 = *(const float2*)&be[colh * 64 + col];
                float2 b0 = make_float2(acc[nt * 4 + 0], acc[nt * 4 + 1]);
                float2 b1 = make_float2(acc[nt * 4 + 2], acc[nt * 4 + 3]);
                *(float2*)&B0[col] = b0;
                *(float2*)&B1[col] = b1;
                float2 a0 = *(const float2*)&exch[r0 * 128 + colh * 64 + col];
                float2 a1 = *(const float2*)&exch[r1 * 128 + colh * 64 + col];
                float2 s0 = make_float2(mish1(a0.x + b0.x + be2.x), mish1(a0.y + b0.y + be2.y));
                float2 s1 = make_float2(mish1(a1.x + b1.x + be2.x), mish1(a1.y + b1.y + be2.y));
                *(float2*)&S0[col] = s0;
                *(float2*)&S1[col] = s1;
            }
        }
        __syncthreads();
    }
}

// ---------------- kernel 4: edges ----------------
__global__ __launch_bounds__(256) void k_edge(
    const void* __restrict__ ei, const float* __restrict__ be,
    float* __restrict__ edge_out, int E)
{
    int is64 = d_is64[1];
    int lane = threadIdx.x & 31;
    int warp = blockIdx.x * (blockDim.x >> 5) + (threadIdx.x >> 5);
    int nwarps = gridDim.x * (blockDim.x >> 5);
    int c = lane * 4;
    float4 be4 = __ldg((const float4*)&be[c]);
    int pairs = E >> 1;
    for (int p = warp; p < pairs; p += nwarps) {
        long e0 = 2L * p;
        long s0 = ldx(ei, e0, is64);
        long s1 = ldx(ei, e0 + 1, is64);
        long d0 = ldx(ei, (long)E + e0, is64);
        long d1 = ldx(ei, (long)E + e0 + 1, is64);
        float4 a0 = __ldg((const float4*)&g_A[(size_t)s0 * D + c]);
        float4 b0 = __ldg((const float4*)&g_B[(size_t)d0 * D + c]);
        float4 a1 = __ldg((const float4*)&g_A[(size_t)s1 * D + c]);
        float4 b1 = __ldg((const float4*)&g_B[(size_t)d1 * D + c]);
        float4 v0 = mish4(make_float4(a0.x + b0.x + be4.x, a0.y + b0.y + be4.y,
                                      a0.z + b0.z + be4.z, a0.w + b0.w + be4.w));
        float4 v1 = mish4(make_float4(a1.x + b1.x + be4.x, a1.y + b1.y + be4.y,
                                      a1.z + b1.z + be4.z, a1.w + b1.w + be4.w));
        float4 o = make_float4(0.5f * (v0.x + v1.x), 0.5f * (v0.y + v1.y),
                               0.5f * (v0.z + v1.z), 0.5f * (v0.w + v1.w));
        *(float4*)&edge_out[(size_t)p * D + c] = o;
    }
}

// ---------------- launch ----------------
extern "C" void kernel_launch(void* const* d_in, const int* in_sizes, int n_in,
                              void* d_out, int out_size)
{
    const float* x     = (const float*)d_in[0];
    const void*  batch = d_in[1];
    const void*  ei    = d_in[2];
    const float* Wn    = (const float*)d_in[3];
    const float* bn    = (const float*)d_in[4];
    const float* We    = (const float*)d_in[5];
    const float* bee   = (const float*)d_in[6];
    const float* Wp    = (const float*)d_in[7];
    const float* bp    = (const float*)d_in[8];

    int N = in_sizes[0] / D;
    int E = MAXE;

    float* out       = (float*)d_out;
    float* node_out  = out;
    float* self_out  = out + (size_t)N * D;
    float* edge_out  = out + 2 * (size_t)N * D;
    float* graph_out = out + 3 * (size_t)N * D;

    static int init_done = 0;
    if (!init_done) {
        cudaFuncSetAttribute(k_f1, cudaFuncAttributeMaxDynamicSharedMemorySize, F1_SMEM);
        cudaFuncSetAttribute(k_f2, cudaFuncAttributeMaxDynamicSharedMemorySize, F2_SMEM);
        init_done = 1;
    }

    k_detect<<<1, 32>>>((const unsigned*)batch, N, (const unsigned*)ei);
    k_pool<<<NG, 128>>>(x, batch, N);
    k_graphmm<<<NG / 64, 256>>>(Wn, bn, Wp, bp, graph_out, NG);
    k_f1<<<148, 1024, F1_SMEM>>>(x, batch, Wn, node_out, N);
    k_f2<<<148, 1024, F2_SMEM>>>(node_out, We, bee, self_out, N);
    k_edge<<<2048, 256>>>(ei, bee, edge_out, E);
}